// round 15
// baseline (speedup 1.0000x reference)
#include <cuda_runtime.h>
#include <cuda_bf16.h>
#include <math.h>

#define FULLMASK 0xffffffffu
typedef unsigned int u32;

#define NPIX (512 * 12288)
#define X2S 50                 // X2 row stride in u32 (conflict-free, uint2-aligned)

// ---------------- device scratch (no runtime allocation allowed) -------------
__device__ u32 g_wh[9 * 192 * 96];   // conv3 W bf16-hi pairs [tap][o][kp]
__device__ u32 g_wl[9 * 192 * 96];   // conv3 W bf16-lo pairs
__device__ u32 g_w2h[9 * 48 * 24];   // conv2 W bf16-hi pairs [tap][o][kp]
__device__ u32 g_w2l[9 * 48 * 24];   // conv2 W bf16-lo pairs
__device__ float g_w3d[192];         // conv3 center-diag bf16-hi (as float)
__device__ float g_w2d[48];          // conv2 center-diag bf16-hi (as float)
__device__ float g_convld;           // sum of conv_logdet over the 3 layers

// ---------------- helpers -----------------------------------------------------
__device__ __forceinline__ void bsplit(float x, unsigned short& h, unsigned short& l) {
  __nv_bfloat16 bh = __float2bfloat16(x);
  float r = x - __bfloat162float(bh);
  __nv_bfloat16 bl = __float2bfloat16(r);
  h = __bfloat16_as_ushort(bh);
  l = __bfloat16_as_ushort(bl);
}
__device__ __forceinline__ u32 hilo32(float x) {
  unsigned short h, l;
  bsplit(x, h, l);
  return (u32)h | ((u32)l << 16);
}
__device__ __forceinline__ float bf16f(float x) {
  return __bfloat162float(__float2bfloat16(x));
}
__device__ __forceinline__ void mma_bf16(float* d, u32 a0, u32 a1, u32 a2, u32 a3,
                                         u32 b0, u32 b1) {
  asm volatile(
      "mma.sync.aligned.m16n8k16.row.col.f32.bf16.bf16.f32 "
      "{%0,%1,%2,%3}, {%4,%5,%6,%7}, {%8,%9}, {%0,%1,%2,%3};"
      : "+f"(d[0]), "+f"(d[1]), "+f"(d[2]), "+f"(d[3])
      : "r"(a0), "r"(a1), "r"(a2), "r"(a3), "r"(b0), "r"(b1));
}

// ============================================================================
// conv_logdet: exact frequency-sum of the 2nd-order log det expansion
// ============================================================================
__device__ __forceinline__ float cld_partial_strided(const float* __restrict__ K,
                                                     int c, int n, int base, int stride) {
  float s = 0.f;
  for (int oi = base; oi < c * c; oi += stride) {
    int o = oi / c, i = oi - o * c;
    const float* Koi = K + (o * c + i) * 9;
    const float* Kio = K + (i * c + o) * 9;
    bool diag = (o == i);
    if (diag) s += Koi[4] - 1.0f;
    float t2 = 0.f;
#pragma unroll
    for (int st = 0; st < 9; st++) {
      float m1 = __ldg(Koi + st);
      float m2 = __ldg(Kio + 8 - st);
      if (diag && st == 4) { m1 -= 1.0f; m2 -= 1.0f; }
      t2 = fmaf(m1, m2, t2);
    }
    s -= 0.5f * t2;
  }
  return s * (float)(n * n);
}

__global__ void k_logdet(const float* __restrict__ k1, const float* __restrict__ k2,
                         const float* __restrict__ k3) {
  int base = blockIdx.x * 256 + threadIdx.x;
  int stride = gridDim.x * 256;
  float s = cld_partial_strided(k3, 192, 8, base, stride)
          + cld_partial_strided(k2, 48, 16, base, stride)
          + cld_partial_strided(k1, 12, 32, base, stride);
  __shared__ float red[8];
  int lane = threadIdx.x & 31, wid = threadIdx.x >> 5;
#pragma unroll
  for (int off = 16; off > 0; off >>= 1) s += __shfl_down_sync(FULLMASK, s, off);
  if (lane == 0) red[wid] = s;
  __syncthreads();
  if (threadIdx.x == 0) {
    float t = 0.f;
#pragma unroll
    for (int i = 0; i < 8; i++) t += red[i];
    atomicAdd(&g_convld, t);
  }
}

// pack conv2+conv3 weights into hi/lo bf16 pair words; diag arrays; zero convld
__global__ void k_pack(const float* __restrict__ k2, const float* __restrict__ k3) {
  int idx = blockIdx.x * 256 + threadIdx.x;
  if (idx == 0) g_convld = 0.f;
  if (idx < 192) g_w3d[idx] = bf16f(k3[(idx * 192 + idx) * 9 + 4]);
  if (idx < 48)  g_w2d[idx] = bf16f(k2[(idx * 48 + idx) * 9 + 4]);
  if (idx < 9 * 48 * 24) {
    int tap = idx / (48 * 24);
    int rem = idx - tap * 48 * 24;
    int o = rem / 24, kp = rem - o * 24;
    float v0 = k2[(o * 48 + 2 * kp) * 9 + tap];
    float v1 = k2[(o * 48 + 2 * kp + 1) * 9 + tap];
    unsigned short h0, l0, h1, l1;
    bsplit(v0, h0, l0);
    bsplit(v1, h1, l1);
    g_w2h[idx] = (u32)h0 | ((u32)h1 << 16);
    g_w2l[idx] = (u32)l0 | ((u32)l1 << 16);
  }
  if (idx < 9 * 192 * 96) {
    int tap = idx / (192 * 96);
    int rem = idx - tap * 192 * 96;
    int o = rem / 96, kp = rem - o * 96;
    float v0 = k3[(o * 192 + 2 * kp) * 9 + tap];
    float v1 = k3[(o * 192 + 2 * kp + 1) * 9 + tap];
    unsigned short h0, l0, h1, l1;
    bsplit(v0, h0, l0);
    bsplit(v1, h1, l1);
    g_wh[idx] = (u32)h0 | ((u32)h1 << 16);
    g_wl[idx] = (u32)l0 | ((u32)l1 << 16);
  }
}

// ============================================================================
// data-path helpers
// ============================================================================
__device__ __forceinline__ float lrelu_ld(float v, float& y) {
  float vp = fmaxf(v, 0.f);
  y = fmaf(1.2f, vp, 0.8f * (v - vp));
  float g = vp / (v + 0.001f);
  // reference: yd = 1.2*g; yd = yd + 0.8*(1-yd)  ->  0.8 + 0.24*g
  return __logf(fmaf(0.24f, g, 0.8f));
}

// conv1: 12->12 circular on 32x32 (one warp per output plane); writes packed
// hi/lo bf16 im2col X2[m=256][k=48] (row stride X2S, conflict-free)
__device__ __forceinline__ float conv1_plane(const float* __restrict__ A, u32* __restrict__ X2,
                                             const float* __restrict__ k1, float bias,
                                             int o, int lane) {
  float acc[32];
#pragma unroll
  for (int h = 0; h < 32; h++) acc[h] = 0.f;
#pragma unroll 1
  for (int i = 0; i < 12; i++) {
    const float* W = k1 + (o * 12 + i) * 9;
    float w0 = __ldg(W + 0), w1 = __ldg(W + 1), w2 = __ldg(W + 2);
    float w3 = __ldg(W + 3), w4 = __ldg(W + 4), w5 = __ldg(W + 5);
    float w6 = __ldg(W + 6), w7 = __ldg(W + 7), w8 = __ldg(W + 8);
    const float* rb = A + i * 1024;
    float am = rb[31 * 32 + lane];
    float a0 = rb[lane];
    float aml = __shfl_sync(FULLMASK, am, (lane + 31) & 31);
    float amr = __shfl_sync(FULLMASK, am, (lane + 1) & 31);
    float a0l = __shfl_sync(FULLMASK, a0, (lane + 31) & 31);
    float a0r = __shfl_sync(FULLMASK, a0, (lane + 1) & 31);
#pragma unroll
    for (int h = 0; h < 32; h++) {
      float ap  = rb[((h + 1) & 31) * 32 + lane];
      float apl = __shfl_sync(FULLMASK, ap, (lane + 31) & 31);
      float apr = __shfl_sync(FULLMASK, ap, (lane + 1) & 31);
      float a = acc[h];
      a = fmaf(w0, aml, a); a = fmaf(w1, am, a); a = fmaf(w2, amr, a);
      a = fmaf(w3, a0l, a); a = fmaf(w4, a0, a); a = fmaf(w5, a0r, a);
      a = fmaf(w6, apl, a); a = fmaf(w7, ap, a); a = fmaf(w8, apr, a);
      acc[h] = a;
      am = a0; aml = a0l; amr = a0r;
      a0 = ap; a0l = apl; a0r = apr;
    }
  }
  float ld = 0.f;
#pragma unroll
  for (int h = 0; h < 32; h++) {
    float y;
    ld += lrelu_ld(acc[h] + bias, y);
    int c2 = o * 4 + ((h & 1) << 1) + (lane & 1);
    int m2 = (h >> 1) * 16 + (lane >> 1);
    X2[m2 * X2S + c2] = hilo32(y);
  }
  return ld;
}

// conv2 via bf16 mma.sync: M=256, N=48, K=48, 9 taps, 2 terms + diag correction.
// Warp wid handles image rows h in {2wid, 2wid+1}; writes X3 im2col packed.
__device__ __forceinline__ float conv2_mma(const u32* __restrict__ X2, u32* __restrict__ X3,
                                           const float* __restrict__ b2, int tid) {
  int wid = tid >> 5, lane = tid & 31;
  int g = lane >> 2, t4 = lane & 3;
  float d[6][2][4];
#pragma unroll
  for (int nt = 0; nt < 6; nt++)
#pragma unroll
    for (int mtl = 0; mtl < 2; mtl++)
#pragma unroll
      for (int q = 0; q < 4; q++) d[nt][mtl][q] = 0.f;

#pragma unroll 1
  for (int tap = 0; tap < 9; tap++) {
    int dy = tap / 3, dx = tap - dy * 3;
    int hs0 = ((2 * wid) + dy + 15) & 15;
    int hs1 = ((2 * wid + 1) + dy + 15) & 15;
    int wa = (g + dx + 15) & 15;
    int wb = (g + 8 + dx + 15) & 15;
    int r00 = hs0 * 16 + wa, r01 = hs0 * 16 + wb;
    int r10 = hs1 * 16 + wa, r11 = hs1 * 16 + wb;
#pragma unroll
    for (int kt = 0; kt < 3; kt++) {
      u32 bh[6][2], bl[6][2];
#pragma unroll
      for (int nt = 0; nt < 6; nt++) {
        int base = tap * 1152 + (nt * 8 + g) * 24 + kt * 8 + t4;
        bh[nt][0] = __ldg(g_w2h + base);
        bh[nt][1] = __ldg(g_w2h + base + 4);
        bl[nt][0] = __ldg(g_w2l + base);
        bl[nt][1] = __ldg(g_w2l + base + 4);
      }
      int k0 = kt * 16 + t4 * 2;
#pragma unroll
      for (int mtl = 0; mtl < 2; mtl++) {
        int ra = mtl ? r10 : r00;
        int rb = mtl ? r11 : r01;
        uint2 p00 = *(const uint2*)(X2 + ra * X2S + k0);
        uint2 p08 = *(const uint2*)(X2 + ra * X2S + k0 + 8);
        uint2 p10 = *(const uint2*)(X2 + rb * X2S + k0);
        uint2 p18 = *(const uint2*)(X2 + rb * X2S + k0 + 8);
        u32 a0 = __byte_perm(p00.x, p00.y, 0x5410);
        u32 a1 = __byte_perm(p10.x, p10.y, 0x5410);
        u32 a2 = __byte_perm(p08.x, p08.y, 0x5410);
        u32 a3 = __byte_perm(p18.x, p18.y, 0x5410);
#pragma unroll
        for (int nt = 0; nt < 6; nt++) {
          mma_bf16(d[nt][mtl], a0, a1, a2, a3, bh[nt][0], bh[nt][1]);
          mma_bf16(d[nt][mtl], a0, a1, a2, a3, bl[nt][0], bl[nt][1]);
        }
      }
    }
  }

  // epilogue: diag correction + bias + lrelu + logdet, write X3 packed
  float ld = 0.f;
#pragma unroll
  for (int nt = 0; nt < 6; nt++) {
    int n0 = nt * 8 + t4 * 2;
    float w2d0 = __ldg(g_w2d + n0), w2d1 = __ldg(g_w2d + n0 + 1);
    float bias0 = __ldg(b2 + n0), bias1 = __ldg(b2 + n0 + 1);
#pragma unroll
    for (int mtl = 0; mtl < 2; mtl++) {
      int h = 2 * wid + mtl;
#pragma unroll
      for (int half = 0; half < 2; half++) {
        int w = g + half * 8;
        int rowb = (h * 16 + w) * X2S;
        u32 wd0 = X2[rowb + n0];
        u32 wd1 = X2[rowb + n0 + 1];
        float xl0 = __uint_as_float(wd0 & 0xFFFF0000u);
        float xl1 = __uint_as_float(wd1 & 0xFFFF0000u);
        float y0 = d[nt][mtl][half * 2]     + fmaf(xl0, w2d0, bias0);
        float y1 = d[nt][mtl][half * 2 + 1] + fmaf(xl1, w2d1, bias1);
        float z0, z1;
        ld += lrelu_ld(y0, z0);
        ld += lrelu_ld(y1, z1);
        int m3 = (h >> 1) * 8 + (w >> 1);
        int sw = (m3 & 3) << 3;
        int c30 = n0 * 4 + ((h & 1) << 1) + (w & 1);
        int c31 = c30 + 4;
        X3[m3 * 192 + (c30 ^ sw)] = hilo32(z0);
        X3[m3 * 192 + (c31 ^ sw)] = hilo32(z1);
      }
    }
  }
  return ld;
}

// circular-shifted row index for conv3 tap (dy,dx) on the 8x8 grid
__device__ __forceinline__ int shrow(int m, int dy, int dx) {
  int hh = m >> 3, ww = m & 7;
  return (((hh + dy + 7) & 7) << 3) | ((ww + dx + 7) & 7);
}

// ============================================================================
// fused per-sample pipeline: one CTA per batch sample
// ============================================================================
__global__ void __launch_bounds__(256, 2) k_main(
    const float* __restrict__ x,
    const float* __restrict__ k1, const float* __restrict__ b1,
    const float* __restrict__ b2,
    const float* __restrict__ b3,
    float* __restrict__ out)
{
  extern __shared__ float smem[];
  float* bufA = smem;                       // 12288 floats (conv1 in; then X3)
  u32* X2 = (u32*)(smem + 12288);           // 12800 u32 (X2 im2col, stride 50)
  __shared__ float red[8];

  int b = blockIdx.x;
  int tid = threadIdx.x;
  int wid = tid >> 5, lane = tid & 31;
  const float* xb = x + (size_t)b * 12288;
  float ldsum = 0.f;

  // ---- stage 0: logit + squeeze -> bufA (12,32,32) ----
#pragma unroll 4
  for (int k = 0; k < 48; k++) {
    int idx = tid + k * 256;
    float v  = xb[idx];
    float xs = fmaf(v, 0.999f, 0.0005f);
    float la = __logf(xs);
    float lb = __logf(1.0f - xs);
    ldsum -= (la + lb);
    int c = idx >> 12;
    int rem = idx & 4095;
    int h = rem >> 6, w = rem & 63;
    bufA[(c * 4 + ((h & 1) << 1) + (w & 1)) * 1024 + (h >> 1) * 32 + (w >> 1)] = la - lb;
  }
  __syncthreads();

  // ---- conv1 + lrelu + squeeze -> X2 (packed hi/lo bf16) ----
  ldsum += conv1_plane(bufA, X2, k1, __ldg(b1 + wid), wid, lane);
  if (wid < 4)
    ldsum += conv1_plane(bufA, X2, k1, __ldg(b1 + 8 + wid), 8 + wid, lane);
  __syncthreads();

  // ---- conv2 (mma.sync) + lrelu + squeeze -> X3 (packed, in bufA) ----
  u32* X = (u32*)bufA;
  ldsum += conv2_mma(X2, X, b2, tid);
  __syncthreads();

  // ---- conv3: bf16 mma.sync implicit GEMM, 2 terms + diag correction ----
  {
    int g  = lane >> 2;            // 0..7
    int t4 = lane & 3;             // 0..3
    float d[3][4][4];
#pragma unroll
    for (int nt = 0; nt < 3; nt++)
#pragma unroll
      for (int mt = 0; mt < 4; mt++)
#pragma unroll
        for (int q = 0; q < 4; q++) d[nt][mt][q] = 0.f;

#pragma unroll 1
    for (int tap = 0; tap < 9; tap++) {
      int dy = tap / 3, dx = tap - dy * 3;
      int r0[4], r1[4], sw[4];
#pragma unroll
      for (int mt = 0; mt < 4; mt++) {
        r0[mt] = shrow(mt * 16 + g, dy, dx);
        r1[mt] = shrow(mt * 16 + g + 8, dy, dx);
        sw[mt] = (r0[mt] & 3) << 3;          // (r1&3) == (r0&3): same w-shift
      }
#pragma unroll 2
      for (int kt = 0; kt < 12; kt++) {
        u32 bh[3][2], bl[3][2];
#pragma unroll
        for (int nt = 0; nt < 3; nt++) {
          int n = (wid * 3 + nt) * 8 + g;
          int base = (tap * 192 + n) * 96 + kt * 8 + t4;
          bh[nt][0] = __ldg(g_wh + base);
          bh[nt][1] = __ldg(g_wh + base + 4);
          bl[nt][0] = __ldg(g_wl + base);
          bl[nt][1] = __ldg(g_wl + base + 4);
        }
#pragma unroll
        for (int mt = 0; mt < 4; mt++) {
          int kb = kt * 16 + t4 * 2;
          int k0 = kb ^ sw[mt];
          int k8 = (kb + 8) ^ sw[mt];
          uint2 p00 = *(const uint2*)(X + r0[mt] * 192 + k0);
          uint2 p08 = *(const uint2*)(X + r0[mt] * 192 + k8);
          uint2 p10 = *(const uint2*)(X + r1[mt] * 192 + k0);
          uint2 p18 = *(const uint2*)(X + r1[mt] * 192 + k8);
          u32 a0h = __byte_perm(p00.x, p00.y, 0x5410);
          u32 a1h = __byte_perm(p10.x, p10.y, 0x5410);
          u32 a2h = __byte_perm(p08.x, p08.y, 0x5410);
          u32 a3h = __byte_perm(p18.x, p18.y, 0x5410);
#pragma unroll
          for (int nt = 0; nt < 3; nt++) {
            mma_bf16(d[nt][mt], a0h, a1h, a2h, a3h, bh[nt][0], bh[nt][1]);
            mma_bf16(d[nt][mt], a0h, a1h, a2h, a3h, bl[nt][0], bl[nt][1]);
          }
        }
      }
    }

    // epilogue: diag correction + bias, y^2 logdet, store
    float* ob = out + (size_t)b * 12288;
#pragma unroll
    for (int nt = 0; nt < 3; nt++) {
      int n = (wid * 3 + nt) * 8 + t4 * 2;
      float bias0 = __ldg(b3 + n), bias1 = __ldg(b3 + n + 1);
      float w3d0 = __ldg(g_w3d + n), w3d1 = __ldg(g_w3d + n + 1);
#pragma unroll
      for (int mt = 0; mt < 4; mt++) {
        int m0 = mt * 16 + g, m1 = m0 + 8;
        int s0 = (m0 & 3) << 3, s1 = (m1 & 3) << 3;
        float xl00 = __uint_as_float(X[m0 * 192 + (n ^ s0)] & 0xFFFF0000u);
        float xl01 = __uint_as_float(X[m0 * 192 + ((n + 1) ^ s0)] & 0xFFFF0000u);
        float xl10 = __uint_as_float(X[m1 * 192 + (n ^ s1)] & 0xFFFF0000u);
        float xl11 = __uint_as_float(X[m1 * 192 + ((n + 1) ^ s1)] & 0xFFFF0000u);
        float y00 = d[nt][mt][0] + fmaf(xl00, w3d0, bias0);
        float y01 = d[nt][mt][1] + fmaf(xl01, w3d1, bias1);
        float y10 = d[nt][mt][2] + fmaf(xl10, w3d0, bias0);
        float y11 = d[nt][mt][3] + fmaf(xl11, w3d1, bias1);
        ldsum -= 0.5f * (y00 * y00 + y01 * y01 + y10 * y10 + y11 * y11);
        ob[n * 64 + m0]       = y00;
        ob[(n + 1) * 64 + m0] = y01;
        ob[n * 64 + m1]       = y10;
        ob[(n + 1) * 64 + m1] = y11;
      }
    }
  }

  // ---- per-sample log_pdf reduction ----
#pragma unroll
  for (int off = 16; off > 0; off >>= 1) ldsum += __shfl_down_sync(FULLMASK, ldsum, off);
  if (lane == 0) red[wid] = ldsum;
  __syncthreads();
  if (tid == 0) {
    float t = 0.f;
#pragma unroll
    for (int i = 0; i < 8; i++) t += red[i];
    out[NPIX + b] = t - 0.5f * 1.8378770664093453f * 12288.0f + g_convld;
  }
}

// ============================================================================
extern "C" void kernel_launch(void* const* d_in, const int* in_sizes, int n_in,
                              void* d_out, int out_size) {
  // map inputs by element count (all sizes distinct) — robust to ordering
  const float *x = 0, *k1 = 0, *b1 = 0, *k2 = 0, *b2 = 0, *k3 = 0, *b3 = 0;
  for (int i = 0; i < n_in; i++) {
    const float* p = (const float*)d_in[i];
    switch (in_sizes[i]) {
      case 512 * 12288:   x  = p; break;
      case 12 * 12 * 9:   k1 = p; break;
      case 12:            b1 = p; break;
      case 48 * 48 * 9:   k2 = p; break;
      case 48:            b2 = p; break;
      case 192 * 192 * 9: k3 = p; break;
      case 192:           b3 = p; break;
    }
  }
  float* out = (float*)d_out;

  const int SMEM_BYTES = (12288 + 256 * X2S) * 4;   // 100352
  cudaFuncSetAttribute(k_main, cudaFuncAttributeMaxDynamicSharedMemorySize, SMEM_BYTES);

  k_pack<<<(9 * 192 * 96 + 255) / 256, 256>>>(k2, k3);   // also zeroes g_convld
  k_logdet<<<160, 256>>>(k1, k2, k3);
  k_main<<<512, 256, SMEM_BYTES>>>(x, k1, b1, b2, b3, out);
}

// round 16
// speedup vs baseline: 1.1982x; 1.1982x over previous
#include <cuda_runtime.h>
#include <cuda_bf16.h>
#include <math.h>

#define FULLMASK 0xffffffffu
typedef unsigned int u32;

#define NPIX (512 * 12288)

// ---------------- device scratch (no runtime allocation allowed) -------------
__device__ u32 g_wh[9 * 192 * 96];   // conv3 W bf16-hi pairs [tap][o][kp]
__device__ u32 g_wl[9 * 192 * 96];   // conv3 W bf16-lo pairs
__device__ float g_w3d[192];         // conv3 center-diag bf16-hi (as float)
__device__ float g_convld;           // sum of conv_logdet over the 3 layers

// ---------------- helpers -----------------------------------------------------
__device__ __forceinline__ void bsplit(float x, unsigned short& h, unsigned short& l) {
  __nv_bfloat16 bh = __float2bfloat16(x);
  float r = x - __bfloat162float(bh);
  __nv_bfloat16 bl = __float2bfloat16(r);
  h = __bfloat16_as_ushort(bh);
  l = __bfloat16_as_ushort(bl);
}
__device__ __forceinline__ u32 hilo32(float x) {
  unsigned short h, l;
  bsplit(x, h, l);
  return (u32)h | ((u32)l << 16);
}
__device__ __forceinline__ float bf16f(float x) {
  return __bfloat162float(__float2bfloat16(x));
}
__device__ __forceinline__ void mma_bf16(float* d, u32 a0, u32 a1, u32 a2, u32 a3,
                                         u32 b0, u32 b1) {
  asm volatile(
      "mma.sync.aligned.m16n8k16.row.col.f32.bf16.bf16.f32 "
      "{%0,%1,%2,%3}, {%4,%5,%6,%7}, {%8,%9}, {%0,%1,%2,%3};"
      : "+f"(d[0]), "+f"(d[1]), "+f"(d[2]), "+f"(d[3])
      : "r"(a0), "r"(a1), "r"(a2), "r"(a3), "r"(b0), "r"(b1));
}

// ============================================================================
// conv_logdet: exact frequency-sum of the 2nd-order log det expansion
// ============================================================================
__device__ __forceinline__ float cld_partial_strided(const float* __restrict__ K,
                                                     int c, int n, int base, int stride) {
  float s = 0.f;
  for (int oi = base; oi < c * c; oi += stride) {
    int o = oi / c, i = oi - o * c;
    const float* Koi = K + (o * c + i) * 9;
    const float* Kio = K + (i * c + o) * 9;
    bool diag = (o == i);
    if (diag) s += Koi[4] - 1.0f;
    float t2 = 0.f;
#pragma unroll
    for (int st = 0; st < 9; st++) {
      float m1 = __ldg(Koi + st);
      float m2 = __ldg(Kio + 8 - st);
      if (diag && st == 4) { m1 -= 1.0f; m2 -= 1.0f; }
      t2 = fmaf(m1, m2, t2);
    }
    s -= 0.5f * t2;
  }
  return s * (float)(n * n);
}

__global__ void k_logdet(const float* __restrict__ k1, const float* __restrict__ k2,
                         const float* __restrict__ k3) {
  int base = blockIdx.x * 256 + threadIdx.x;
  int stride = gridDim.x * 256;
  float s = cld_partial_strided(k3, 192, 8, base, stride)
          + cld_partial_strided(k2, 48, 16, base, stride)
          + cld_partial_strided(k1, 12, 32, base, stride);
  __shared__ float red[8];
  int lane = threadIdx.x & 31, wid = threadIdx.x >> 5;
#pragma unroll
  for (int off = 16; off > 0; off >>= 1) s += __shfl_down_sync(FULLMASK, s, off);
  if (lane == 0) red[wid] = s;
  __syncthreads();
  if (threadIdx.x == 0) {
    float t = 0.f;
#pragma unroll
    for (int i = 0; i < 8; i++) t += red[i];
    atomicAdd(&g_convld, t);
  }
}

// pack conv3 weights: K3[o][i][tap] -> hi/lo bf16 pair words [tap][o][kp(i/2)]
__global__ void k_pack(const float* __restrict__ k3) {
  int idx = blockIdx.x * 256 + threadIdx.x;
  if (idx == 0) g_convld = 0.f;
  if (idx < 192) g_w3d[idx] = bf16f(k3[(idx * 192 + idx) * 9 + 4]);
  if (idx >= 9 * 192 * 96) return;
  int tap = idx / (192 * 96);
  int rem = idx - tap * 192 * 96;
  int o = rem / 96, kp = rem - o * 96;
  float v0 = k3[(o * 192 + 2 * kp) * 9 + tap];
  float v1 = k3[(o * 192 + 2 * kp + 1) * 9 + tap];
  unsigned short h0, l0, h1, l1;
  bsplit(v0, h0, l0);
  bsplit(v1, h1, l1);
  g_wh[idx] = (u32)h0 | ((u32)h1 << 16);
  g_wl[idx] = (u32)l0 | ((u32)l1 << 16);
}

// ============================================================================
// data-path helpers
// ============================================================================
__device__ __forceinline__ float lrelu_ld(float v, float& y) {
  float vp = fmaxf(v, 0.f);
  y = fmaf(1.2f, vp, 0.8f * (v - vp));
  float g = vp / (v + 0.001f);
  // reference: yd = 1.2*g; yd = yd + 0.8*(1-yd)  ->  0.8 + 0.24*g
  return __logf(fmaf(0.24f, g, 0.8f));
}

// conv1: 12->12 circular on 32x32 (one warp per output plane)
__device__ __forceinline__ float conv1_plane(const float* __restrict__ A, float* __restrict__ B,
                                             const float* __restrict__ k1, float bias,
                                             int o, int lane) {
  float acc[32];
#pragma unroll
  for (int h = 0; h < 32; h++) acc[h] = 0.f;
#pragma unroll 1
  for (int i = 0; i < 12; i++) {
    const float* W = k1 + (o * 12 + i) * 9;
    float w0 = __ldg(W + 0), w1 = __ldg(W + 1), w2 = __ldg(W + 2);
    float w3 = __ldg(W + 3), w4 = __ldg(W + 4), w5 = __ldg(W + 5);
    float w6 = __ldg(W + 6), w7 = __ldg(W + 7), w8 = __ldg(W + 8);
    const float* rb = A + i * 1024;
    float am = rb[31 * 32 + lane];
    float a0 = rb[lane];
    float aml = __shfl_sync(FULLMASK, am, (lane + 31) & 31);
    float amr = __shfl_sync(FULLMASK, am, (lane + 1) & 31);
    float a0l = __shfl_sync(FULLMASK, a0, (lane + 31) & 31);
    float a0r = __shfl_sync(FULLMASK, a0, (lane + 1) & 31);
#pragma unroll
    for (int h = 0; h < 32; h++) {
      float ap  = rb[((h + 1) & 31) * 32 + lane];
      float apl = __shfl_sync(FULLMASK, ap, (lane + 31) & 31);
      float apr = __shfl_sync(FULLMASK, ap, (lane + 1) & 31);
      float a = acc[h];
      a = fmaf(w0, aml, a); a = fmaf(w1, am, a); a = fmaf(w2, amr, a);
      a = fmaf(w3, a0l, a); a = fmaf(w4, a0, a); a = fmaf(w5, a0r, a);
      a = fmaf(w6, apl, a); a = fmaf(w7, ap, a); a = fmaf(w8, apr, a);
      acc[h] = a;
      am = a0; aml = a0l; amr = a0r;
      a0 = ap; a0l = apl; a0r = apr;
    }
  }
  float ld = 0.f;
#pragma unroll
  for (int h = 0; h < 32; h++) {
    float y;
    ld += lrelu_ld(acc[h] + bias, y);
    int c2 = o * 4 + ((h & 1) << 1) + (lane & 1);
    B[c2 * 256 + (h >> 1) * 16 + (lane >> 1)] = y;
  }
  return ld;
}

// conv2: 48->48 circular on 16x16 (scalar fp32); writes lrelu(out) into the
// packed hi/lo bf16 im2col matrix X3[m=64][k=192] (k XOR-swizzled by (m&3)<<3).
__device__ __forceinline__ float conv2_triple(const float* __restrict__ B, u32* __restrict__ X,
                                              const float* __restrict__ k2,
                                              const float* __restrict__ b2,
                                              int o0, int lane) {
  int s  = lane >> 4;
  int w  = lane & 15;
  int hb = s * 8;
  float acc[3][8];
#pragma unroll
  for (int oo = 0; oo < 3; oo++)
#pragma unroll
    for (int r = 0; r < 8; r++) acc[oo][r] = 0.f;
#pragma unroll 1
  for (int i = 0; i < 48; i++) {
    float W[3][9];
#pragma unroll
    for (int oo = 0; oo < 3; oo++) {
      const float* Wp = k2 + ((o0 + oo) * 48 + i) * 9;
#pragma unroll
      for (int t = 0; t < 9; t++) W[oo][t] = __ldg(Wp + t);
    }
    const float* rb = B + i * 256;
    float am = rb[((hb + 15) & 15) * 16 + w];
    float a0 = rb[hb * 16 + w];
    float aml = __shfl_sync(FULLMASK, am, (w + 15) & 15, 16);
    float amr = __shfl_sync(FULLMASK, am, (w + 1) & 15, 16);
    float a0l = __shfl_sync(FULLMASK, a0, (w + 15) & 15, 16);
    float a0r = __shfl_sync(FULLMASK, a0, (w + 1) & 15, 16);
#pragma unroll
    for (int r = 0; r < 8; r++) {
      float ap  = rb[((hb + r + 1) & 15) * 16 + w];
      float apl = __shfl_sync(FULLMASK, ap, (w + 15) & 15, 16);
      float apr = __shfl_sync(FULLMASK, ap, (w + 1) & 15, 16);
#pragma unroll
      for (int oo = 0; oo < 3; oo++) {
        float a = acc[oo][r];
        a = fmaf(W[oo][0], aml, a); a = fmaf(W[oo][1], am, a); a = fmaf(W[oo][2], amr, a);
        a = fmaf(W[oo][3], a0l, a); a = fmaf(W[oo][4], a0, a); a = fmaf(W[oo][5], a0r, a);
        a = fmaf(W[oo][6], apl, a); a = fmaf(W[oo][7], ap, a); a = fmaf(W[oo][8], apr, a);
        acc[oo][r] = a;
      }
      am = a0; aml = a0l; amr = a0r;
      a0 = ap; a0l = apl; a0r = apr;
    }
  }
  float ld = 0.f;
#pragma unroll
  for (int oo = 0; oo < 3; oo++) {
    int o = o0 + oo;
    float bias = __ldg(b2 + o);
#pragma unroll
    for (int r = 0; r < 8; r++) {
      int h = hb + r;
      float y;
      ld += lrelu_ld(acc[oo][r] + bias, y);
      int c3 = o * 4 + ((h & 1) << 1) + (w & 1);   // conv3 input channel (k)
      int m = (h >> 1) * 8 + (w >> 1);             // pixel row in X
      X[m * 192 + (c3 ^ ((m & 3) << 3))] = hilo32(y);
    }
  }
  return ld;
}

// circular-shifted row index for tap (dy,dx)
__device__ __forceinline__ int shrow(int m, int dy, int dx) {
  int hh = m >> 3, ww = m & 7;
  return (((hh + dy + 7) & 7) << 3) | ((ww + dx + 7) & 7);
}

// ============================================================================
// fused per-sample pipeline: one CTA per batch sample
// ============================================================================
__global__ void __launch_bounds__(256, 2) k_main(
    const float* __restrict__ x,
    const float* __restrict__ k1, const float* __restrict__ b1,
    const float* __restrict__ k2, const float* __restrict__ b2,
    const float* __restrict__ b3,
    float* __restrict__ out)
{
  extern __shared__ float smem[];
  float* bufA = smem;                 // 12288 floats (conv1 in; then X im2col)
  float* bufB = smem + 12288;         // 12288 floats (conv2 in)
  __shared__ float red[8];

  int b = blockIdx.x;
  int tid = threadIdx.x;
  int wid = tid >> 5, lane = tid & 31;
  const float* xb = x + (size_t)b * 12288;
  float ldsum = 0.f;

  // ---- stage 0: logit + squeeze -> bufA (12,32,32) ----
#pragma unroll 4
  for (int k = 0; k < 48; k++) {
    int idx = tid + k * 256;
    float v  = xb[idx];
    float xs = fmaf(v, 0.999f, 0.0005f);
    float la = __logf(xs);
    float lb = __logf(1.0f - xs);
    ldsum -= (la + lb);
    int c = idx >> 12;
    int rem = idx & 4095;
    int h = rem >> 6, w = rem & 63;
    bufA[(c * 4 + ((h & 1) << 1) + (w & 1)) * 1024 + (h >> 1) * 32 + (w >> 1)] = la - lb;
  }
  __syncthreads();

  // ---- conv1 + lrelu + squeeze -> bufB (48,16,16) ----
  ldsum += conv1_plane(bufA, bufB, k1, __ldg(b1 + wid), wid, lane);
  if (wid < 4)
    ldsum += conv1_plane(bufA, bufB, k1, __ldg(b1 + 8 + wid), 8 + wid, lane);
  __syncthreads();

  // ---- conv2 + lrelu + squeeze -> X (packed hi/lo bf16 im2col in bufA) ----
  u32* X = (u32*)bufA;
  ldsum += conv2_triple(bufB, X, k2, b2, wid * 6,     lane);
  ldsum += conv2_triple(bufB, X, k2, b2, wid * 6 + 3, lane);
  __syncthreads();

  // ---- conv3: bf16 mma.sync implicit GEMM, 2 terms + diag correction ----
  {
    int g  = lane >> 2;            // 0..7
    int t4 = lane & 3;             // 0..3
    float d[3][4][4];
#pragma unroll
    for (int nt = 0; nt < 3; nt++)
#pragma unroll
      for (int mt = 0; mt < 4; mt++)
#pragma unroll
        for (int q = 0; q < 4; q++) d[nt][mt][q] = 0.f;

#pragma unroll 1
    for (int tap = 0; tap < 9; tap++) {
      int dy = tap / 3, dx = tap - dy * 3;
      int r0[4], r1[4], sw[4];
#pragma unroll
      for (int mt = 0; mt < 4; mt++) {
        r0[mt] = shrow(mt * 16 + g, dy, dx);
        r1[mt] = shrow(mt * 16 + g + 8, dy, dx);
        sw[mt] = (r0[mt] & 3) << 3;          // (r1&3) == (r0&3): same w-shift
      }
#pragma unroll 2
      for (int kt = 0; kt < 12; kt++) {
        // B fragments: hi and lo, 3 n-tiles
        u32 bh[3][2], bl[3][2];
#pragma unroll
        for (int nt = 0; nt < 3; nt++) {
          int n = (wid * 3 + nt) * 8 + g;
          int base = (tap * 192 + n) * 96 + kt * 8 + t4;
          bh[nt][0] = __ldg(g_wh + base);
          bh[nt][1] = __ldg(g_wh + base + 4);
          bl[nt][0] = __ldg(g_wl + base);
          bl[nt][1] = __ldg(g_wl + base + 4);
        }
#pragma unroll
        for (int mt = 0; mt < 4; mt++) {
          int kb = kt * 16 + t4 * 2;
          int k0 = kb ^ sw[mt];
          int k8 = (kb + 8) ^ sw[mt];
          uint2 p00 = *(const uint2*)(X + r0[mt] * 192 + k0);
          uint2 p08 = *(const uint2*)(X + r0[mt] * 192 + k8);
          uint2 p10 = *(const uint2*)(X + r1[mt] * 192 + k0);
          uint2 p18 = *(const uint2*)(X + r1[mt] * 192 + k8);
          u32 a0h = __byte_perm(p00.x, p00.y, 0x5410);
          u32 a1h = __byte_perm(p10.x, p10.y, 0x5410);
          u32 a2h = __byte_perm(p08.x, p08.y, 0x5410);
          u32 a3h = __byte_perm(p18.x, p18.y, 0x5410);
#pragma unroll
          for (int nt = 0; nt < 3; nt++) {
            mma_bf16(d[nt][mt], a0h, a1h, a2h, a3h, bh[nt][0], bh[nt][1]);
            mma_bf16(d[nt][mt], a0h, a1h, a2h, a3h, bl[nt][0], bl[nt][1]);
          }
        }
      }
    }

    // epilogue: diag correction (Al*I) + bias, y^2 logdet, store
    float* ob = out + (size_t)b * 12288;
#pragma unroll
    for (int nt = 0; nt < 3; nt++) {
      int n = (wid * 3 + nt) * 8 + t4 * 2;
      float bias0 = __ldg(b3 + n), bias1 = __ldg(b3 + n + 1);
      float w3d0 = __ldg(g_w3d + n), w3d1 = __ldg(g_w3d + n + 1);
#pragma unroll
      for (int mt = 0; mt < 4; mt++) {
        int m0 = mt * 16 + g, m1 = m0 + 8;
        int s0 = (m0 & 3) << 3, s1 = (m1 & 3) << 3;
        float xl00 = __uint_as_float(X[m0 * 192 + (n ^ s0)] & 0xFFFF0000u);
        float xl01 = __uint_as_float(X[m0 * 192 + ((n + 1) ^ s0)] & 0xFFFF0000u);
        float xl10 = __uint_as_float(X[m1 * 192 + (n ^ s1)] & 0xFFFF0000u);
        float xl11 = __uint_as_float(X[m1 * 192 + ((n + 1) ^ s1)] & 0xFFFF0000u);
        float y00 = d[nt][mt][0] + fmaf(xl00, w3d0, bias0);
        float y01 = d[nt][mt][1] + fmaf(xl01, w3d1, bias1);
        float y10 = d[nt][mt][2] + fmaf(xl10, w3d0, bias0);
        float y11 = d[nt][mt][3] + fmaf(xl11, w3d1, bias1);
        ldsum -= 0.5f * (y00 * y00 + y01 * y01 + y10 * y10 + y11 * y11);
        ob[n * 64 + m0]       = y00;
        ob[(n + 1) * 64 + m0] = y01;
        ob[n * 64 + m1]       = y10;
        ob[(n + 1) * 64 + m1] = y11;
      }
    }
  }

  // ---- per-sample log_pdf reduction ----
#pragma unroll
  for (int off = 16; off > 0; off >>= 1) ldsum += __shfl_down_sync(FULLMASK, ldsum, off);
  if (lane == 0) red[wid] = ldsum;
  __syncthreads();
  if (tid == 0) {
    float t = 0.f;
#pragma unroll
    for (int i = 0; i < 8; i++) t += red[i];
    out[NPIX + b] = t - 0.5f * 1.8378770664093453f * 12288.0f + g_convld;
  }
}

// ============================================================================
extern "C" void kernel_launch(void* const* d_in, const int* in_sizes, int n_in,
                              void* d_out, int out_size) {
  // map inputs by element count (all sizes distinct) — robust to ordering
  const float *x = 0, *k1 = 0, *b1 = 0, *k2 = 0, *b2 = 0, *k3 = 0, *b3 = 0;
  for (int i = 0; i < n_in; i++) {
    const float* p = (const float*)d_in[i];
    switch (in_sizes[i]) {
      case 512 * 12288:   x  = p; break;
      case 12 * 12 * 9:   k1 = p; break;
      case 12:            b1 = p; break;
      case 48 * 48 * 9:   k2 = p; break;
      case 48:            b2 = p; break;
      case 192 * 192 * 9: k3 = p; break;
      case 192:           b3 = p; break;
    }
  }
  float* out = (float*)d_out;

  const int SMEM_BYTES = 2 * 12288 * 4;   // 98304
  cudaFuncSetAttribute(k_main, cudaFuncAttributeMaxDynamicSharedMemorySize, SMEM_BYTES);

  k_pack<<<(9 * 192 * 96 + 255) / 256, 256>>>(k3);   // also zeroes g_convld
  k_logdet<<<160, 256>>>(k1, k2, k3);
  k_main<<<512, 256, SMEM_BYTES>>>(x, k1, b1, k2, b2, b3, out);
}

// round 17
// speedup vs baseline: 1.5182x; 1.2671x over previous
#include <cuda_runtime.h>
#include <cuda_bf16.h>
#include <math.h>

#define FULLMASK 0xffffffffu
typedef unsigned int u32;

#define NPIX (512 * 12288)

// ---------------- device scratch (no runtime allocation allowed) -------------
// conv3 weight fragments, warp-coalesced:
//   g_wf[((tap*8 + warp)*12 + kt)*3 + nt][lane] = {bh0, bh1, bl0, bl1}
__device__ uint4 g_wf[9 * 8 * 12 * 3 * 32];
__device__ float g_w3d[192];         // conv3 center-diag bf16-hi (as float)
__device__ float g_convld;           // sum of conv_logdet over the 3 layers

// ---------------- helpers -----------------------------------------------------
__device__ __forceinline__ void bsplit(float x, unsigned short& h, unsigned short& l) {
  __nv_bfloat16 bh = __float2bfloat16(x);
  float r = x - __bfloat162float(bh);
  __nv_bfloat16 bl = __float2bfloat16(r);
  h = __bfloat16_as_ushort(bh);
  l = __bfloat16_as_ushort(bl);
}
__device__ __forceinline__ u32 hilo32(float x) {
  unsigned short h, l;
  bsplit(x, h, l);
  return (u32)h | ((u32)l << 16);
}
__device__ __forceinline__ float bf16f(float x) {
  return __bfloat162float(__float2bfloat16(x));
}
__device__ __forceinline__ void mma_bf16(float* d, u32 a0, u32 a1, u32 a2, u32 a3,
                                         u32 b0, u32 b1) {
  asm volatile(
      "mma.sync.aligned.m16n8k16.row.col.f32.bf16.bf16.f32 "
      "{%0,%1,%2,%3}, {%4,%5,%6,%7}, {%8,%9}, {%0,%1,%2,%3};"
      : "+f"(d[0]), "+f"(d[1]), "+f"(d[2]), "+f"(d[3])
      : "r"(a0), "r"(a1), "r"(a2), "r"(a3), "r"(b0), "r"(b1));
}

// ============================================================================
// conv_logdet: exact frequency-sum of the 2nd-order log det expansion
// ============================================================================
__device__ __forceinline__ float cld_partial_strided(const float* __restrict__ K,
                                                     int c, int n, int base, int stride) {
  float s = 0.f;
  for (int oi = base; oi < c * c; oi += stride) {
    int o = oi / c, i = oi - o * c;
    const float* Koi = K + (o * c + i) * 9;
    const float* Kio = K + (i * c + o) * 9;
    bool diag = (o == i);
    if (diag) s += Koi[4] - 1.0f;
    float t2 = 0.f;
#pragma unroll
    for (int st = 0; st < 9; st++) {
      float m1 = __ldg(Koi + st);
      float m2 = __ldg(Kio + 8 - st);
      if (diag && st == 4) { m1 -= 1.0f; m2 -= 1.0f; }
      t2 = fmaf(m1, m2, t2);
    }
    s -= 0.5f * t2;
  }
  return s * (float)(n * n);
}

__global__ void k_logdet(const float* __restrict__ k1, const float* __restrict__ k2,
                         const float* __restrict__ k3) {
  int base = blockIdx.x * 256 + threadIdx.x;
  int stride = gridDim.x * 256;
  float s = cld_partial_strided(k3, 192, 8, base, stride)
          + cld_partial_strided(k2, 48, 16, base, stride)
          + cld_partial_strided(k1, 12, 32, base, stride);
  __shared__ float red[8];
  int lane = threadIdx.x & 31, wid = threadIdx.x >> 5;
#pragma unroll
  for (int off = 16; off > 0; off >>= 1) s += __shfl_down_sync(FULLMASK, s, off);
  if (lane == 0) red[wid] = s;
  __syncthreads();
  if (threadIdx.x == 0) {
    float t = 0.f;
#pragma unroll
    for (int i = 0; i < 8; i++) t += red[i];
    atomicAdd(&g_convld, t);
  }
}

// pack conv3 weights into warp-coalesced uint4 fragments + diag; zero convld
__global__ void k_pack(const float* __restrict__ k3) {
  int idx = blockIdx.x * 256 + threadIdx.x;
  if (idx == 0) g_convld = 0.f;
  if (idx < 192) g_w3d[idx] = bf16f(k3[(idx * 192 + idx) * 9 + 4]);
  if (idx >= 9 * 8 * 12 * 3 * 32) return;
  int lane = idx & 31;
  int r = idx >> 5;
  int nt = r % 3;  r /= 3;
  int kt = r % 12; r /= 12;
  int w  = r % 8;  r /= 8;
  int tap = r;
  int g = lane >> 2, t4 = lane & 3;
  int n = (w * 3 + nt) * 8 + g;          // output channel (B row)
  int kp = kt * 8 + t4;                  // pair index: k-channels 2kp, 2kp+1
  float v0 = k3[(n * 192 + 2 * kp) * 9 + tap];
  float v1 = k3[(n * 192 + 2 * kp + 1) * 9 + tap];
  float v2 = k3[(n * 192 + 2 * kp + 8) * 9 + tap];
  float v3 = k3[(n * 192 + 2 * kp + 9) * 9 + tap];
  unsigned short h0, l0, h1, l1, h2, l2, h3, l3;
  bsplit(v0, h0, l0);
  bsplit(v1, h1, l1);
  bsplit(v2, h2, l2);
  bsplit(v3, h3, l3);
  g_wf[idx] = make_uint4((u32)h0 | ((u32)h1 << 16), (u32)h2 | ((u32)h3 << 16),
                         (u32)l0 | ((u32)l1 << 16), (u32)l2 | ((u32)l3 << 16));
}

// ============================================================================
// data-path helpers
// ============================================================================
__device__ __forceinline__ float lrelu_ld(float v, float& y) {
  float vp = fmaxf(v, 0.f);
  y = fmaf(1.2f, vp, 0.8f * (v - vp));
  float g = vp / (v + 0.001f);
  // reference: yd = 1.2*g; yd = yd + 0.8*(1-yd)  ->  0.8 + 0.24*g
  return __logf(fmaf(0.24f, g, 0.8f));
}

// conv1: 12->12 circular on 32x32 (one warp per output plane)
__device__ __forceinline__ float conv1_plane(const float* __restrict__ A, float* __restrict__ B,
                                             const float* __restrict__ k1, float bias,
                                             int o, int lane) {
  float acc[32];
#pragma unroll
  for (int h = 0; h < 32; h++) acc[h] = 0.f;
#pragma unroll 1
  for (int i = 0; i < 12; i++) {
    const float* W = k1 + (o * 12 + i) * 9;
    float w0 = __ldg(W + 0), w1 = __ldg(W + 1), w2 = __ldg(W + 2);
    float w3 = __ldg(W + 3), w4 = __ldg(W + 4), w5 = __ldg(W + 5);
    float w6 = __ldg(W + 6), w7 = __ldg(W + 7), w8 = __ldg(W + 8);
    const float* rb = A + i * 1024;
    float am = rb[31 * 32 + lane];
    float a0 = rb[lane];
    float aml = __shfl_sync(FULLMASK, am, (lane + 31) & 31);
    float amr = __shfl_sync(FULLMASK, am, (lane + 1) & 31);
    float a0l = __shfl_sync(FULLMASK, a0, (lane + 31) & 31);
    float a0r = __shfl_sync(FULLMASK, a0, (lane + 1) & 31);
#pragma unroll
    for (int h = 0; h < 32; h++) {
      float ap  = rb[((h + 1) & 31) * 32 + lane];
      float apl = __shfl_sync(FULLMASK, ap, (lane + 31) & 31);
      float apr = __shfl_sync(FULLMASK, ap, (lane + 1) & 31);
      float a = acc[h];
      a = fmaf(w0, aml, a); a = fmaf(w1, am, a); a = fmaf(w2, amr, a);
      a = fmaf(w3, a0l, a); a = fmaf(w4, a0, a); a = fmaf(w5, a0r, a);
      a = fmaf(w6, apl, a); a = fmaf(w7, ap, a); a = fmaf(w8, apr, a);
      acc[h] = a;
      am = a0; aml = a0l; amr = a0r;
      a0 = ap; a0l = apl; a0r = apr;
    }
  }
  float ld = 0.f;
#pragma unroll
  for (int h = 0; h < 32; h++) {
    float y;
    ld += lrelu_ld(acc[h] + bias, y);
    int c2 = o * 4 + ((h & 1) << 1) + (lane & 1);
    B[c2 * 256 + (h >> 1) * 16 + (lane >> 1)] = y;
  }
  return ld;
}

// conv2: 48->48 circular on 16x16 (scalar fp32); writes lrelu(out) into the
// packed hi/lo bf16 im2col matrix X[m=64][k=192] (k XOR-swizzled by (m&3)<<3).
__device__ __forceinline__ float conv2_triple(const float* __restrict__ B, u32* __restrict__ X,
                                              const float* __restrict__ k2,
                                              const float* __restrict__ b2,
                                              int o0, int lane) {
  int s  = lane >> 4;
  int w  = lane & 15;
  int hb = s * 8;
  float acc[3][8];
#pragma unroll
  for (int oo = 0; oo < 3; oo++)
#pragma unroll
    for (int r = 0; r < 8; r++) acc[oo][r] = 0.f;
#pragma unroll 1
  for (int i = 0; i < 48; i++) {
    float W[3][9];
#pragma unroll
    for (int oo = 0; oo < 3; oo++) {
      const float* Wp = k2 + ((o0 + oo) * 48 + i) * 9;
#pragma unroll
      for (int t = 0; t < 9; t++) W[oo][t] = __ldg(Wp + t);
    }
    const float* rb = B + i * 256;
    float am = rb[((hb + 15) & 15) * 16 + w];
    float a0 = rb[hb * 16 + w];
    float aml = __shfl_sync(FULLMASK, am, (w + 15) & 15, 16);
    float amr = __shfl_sync(FULLMASK, am, (w + 1) & 15, 16);
    float a0l = __shfl_sync(FULLMASK, a0, (w + 15) & 15, 16);
    float a0r = __shfl_sync(FULLMASK, a0, (w + 1) & 15, 16);
#pragma unroll
    for (int r = 0; r < 8; r++) {
      float ap  = rb[((hb + r + 1) & 15) * 16 + w];
      float apl = __shfl_sync(FULLMASK, ap, (w + 15) & 15, 16);
      float apr = __shfl_sync(FULLMASK, ap, (w + 1) & 15, 16);
#pragma unroll
      for (int oo = 0; oo < 3; oo++) {
        float a = acc[oo][r];
        a = fmaf(W[oo][0], aml, a); a = fmaf(W[oo][1], am, a); a = fmaf(W[oo][2], amr, a);
        a = fmaf(W[oo][3], a0l, a); a = fmaf(W[oo][4], a0, a); a = fmaf(W[oo][5], a0r, a);
        a = fmaf(W[oo][6], apl, a); a = fmaf(W[oo][7], ap, a); a = fmaf(W[oo][8], apr, a);
        acc[oo][r] = a;
      }
      am = a0; aml = a0l; amr = a0r;
      a0 = ap; a0l = apl; a0r = apr;
    }
  }
  float ld = 0.f;
#pragma unroll
  for (int oo = 0; oo < 3; oo++) {
    int o = o0 + oo;
    float bias = __ldg(b2 + o);
#pragma unroll
    for (int r = 0; r < 8; r++) {
      int h = hb + r;
      float y;
      ld += lrelu_ld(acc[oo][r] + bias, y);
      int c3 = o * 4 + ((h & 1) << 1) + (w & 1);   // conv3 input channel (k)
      int m = (h >> 1) * 8 + (w >> 1);             // pixel row in X
      X[m * 192 + (c3 ^ ((m & 3) << 3))] = hilo32(y);
    }
  }
  return ld;
}

// circular-shifted row index for tap (dy,dx)
__device__ __forceinline__ int shrow(int m, int dy, int dx) {
  int hh = m >> 3, ww = m & 7;
  return (((hh + dy + 7) & 7) << 3) | ((ww + dx + 7) & 7);
}

// ============================================================================
// fused per-sample pipeline: one CTA per batch sample
// ============================================================================
__global__ void __launch_bounds__(256, 2) k_main(
    const float* __restrict__ x,
    const float* __restrict__ k1, const float* __restrict__ b1,
    const float* __restrict__ k2, const float* __restrict__ b2,
    const float* __restrict__ b3,
    float* __restrict__ out)
{
  extern __shared__ float smem[];
  float* bufA = smem;                 // 12288 floats (conv1 in; then X im2col)
  float* bufB = smem + 12288;         // 12288 floats (conv2 in)
  __shared__ float red[8];

  int b = blockIdx.x;
  int tid = threadIdx.x;
  int wid = tid >> 5, lane = tid & 31;
  const float* xb = x + (size_t)b * 12288;
  float ldsum = 0.f;

  // ---- stage 0: logit + squeeze -> bufA (12,32,32) ----
#pragma unroll 4
  for (int k = 0; k < 48; k++) {
    int idx = tid + k * 256;
    float v  = xb[idx];
    float xs = fmaf(v, 0.999f, 0.0005f);
    float la = __logf(xs);
    float lb = __logf(1.0f - xs);
    ldsum -= (la + lb);
    int c = idx >> 12;
    int rem = idx & 4095;
    int h = rem >> 6, w = rem & 63;
    bufA[(c * 4 + ((h & 1) << 1) + (w & 1)) * 1024 + (h >> 1) * 32 + (w >> 1)] = la - lb;
  }
  __syncthreads();

  // ---- conv1 + lrelu + squeeze -> bufB (48,16,16) ----
  ldsum += conv1_plane(bufA, bufB, k1, __ldg(b1 + wid), wid, lane);
  if (wid < 4)
    ldsum += conv1_plane(bufA, bufB, k1, __ldg(b1 + 8 + wid), 8 + wid, lane);
  __syncthreads();

  // ---- conv2 + lrelu + squeeze -> X (packed hi/lo bf16 im2col in bufA) ----
  u32* X = (u32*)bufA;
  ldsum += conv2_triple(bufB, X, k2, b2, wid * 6,     lane);
  ldsum += conv2_triple(bufB, X, k2, b2, wid * 6 + 3, lane);
  __syncthreads();

  // ---- conv3: bf16 mma.sync implicit GEMM, 2 terms + diag correction ----
  {
    int g  = lane >> 2;            // 0..7
    int t4 = lane & 3;             // 0..3
    float d[3][4][4];
#pragma unroll
    for (int nt = 0; nt < 3; nt++)
#pragma unroll
      for (int mt = 0; mt < 4; mt++)
#pragma unroll
        for (int q = 0; q < 4; q++) d[nt][mt][q] = 0.f;

#pragma unroll 1
    for (int tap = 0; tap < 9; tap++) {
      int dy = tap / 3, dx = tap - dy * 3;
      int r0[4], r1[4], sw[4];
#pragma unroll
      for (int mt = 0; mt < 4; mt++) {
        r0[mt] = shrow(mt * 16 + g, dy, dx);
        r1[mt] = shrow(mt * 16 + g + 8, dy, dx);
        sw[mt] = (r0[mt] & 3) << 3;          // (r1&3) == (r0&3): same w-shift
      }
      const uint4* wf = g_wf + ((tap * 8 + wid) * 12) * 3 * 32 + lane;
#pragma unroll 2
      for (int kt = 0; kt < 12; kt++) {
        // B fragments: one warp-coalesced LDG.128 per n-tile
        u32 bh[3][2], bl[3][2];
#pragma unroll
        for (int nt = 0; nt < 3; nt++) {
          uint4 f = __ldg(wf + (kt * 3 + nt) * 32);
          bh[nt][0] = f.x; bh[nt][1] = f.y;
          bl[nt][0] = f.z; bl[nt][1] = f.w;
        }
#pragma unroll
        for (int mt = 0; mt < 4; mt++) {
          int kb = kt * 16 + t4 * 2;
          int k0 = kb ^ sw[mt];
          int k8 = (kb + 8) ^ sw[mt];
          uint2 p00 = *(const uint2*)(X + r0[mt] * 192 + k0);
          uint2 p08 = *(const uint2*)(X + r0[mt] * 192 + k8);
          uint2 p10 = *(const uint2*)(X + r1[mt] * 192 + k0);
          uint2 p18 = *(const uint2*)(X + r1[mt] * 192 + k8);
          u32 a0h = __byte_perm(p00.x, p00.y, 0x5410);
          u32 a1h = __byte_perm(p10.x, p10.y, 0x5410);
          u32 a2h = __byte_perm(p08.x, p08.y, 0x5410);
          u32 a3h = __byte_perm(p18.x, p18.y, 0x5410);
#pragma unroll
          for (int nt = 0; nt < 3; nt++) {
            mma_bf16(d[nt][mt], a0h, a1h, a2h, a3h, bh[nt][0], bh[nt][1]);
            mma_bf16(d[nt][mt], a0h, a1h, a2h, a3h, bl[nt][0], bl[nt][1]);
          }
        }
      }
    }

    // epilogue: diag correction (Al*I) + bias, y^2 logdet, store
    float* ob = out + (size_t)b * 12288;
#pragma unroll
    for (int nt = 0; nt < 3; nt++) {
      int n = (wid * 3 + nt) * 8 + t4 * 2;
      float bias0 = __ldg(b3 + n), bias1 = __ldg(b3 + n + 1);
      float w3d0 = __ldg(g_w3d + n), w3d1 = __ldg(g_w3d + n + 1);
#pragma unroll
      for (int mt = 0; mt < 4; mt++) {
        int m0 = mt * 16 + g, m1 = m0 + 8;
        int s0 = (m0 & 3) << 3, s1 = (m1 & 3) << 3;
        float xl00 = __uint_as_float(X[m0 * 192 + (n ^ s0)] & 0xFFFF0000u);
        float xl01 = __uint_as_float(X[m0 * 192 + ((n + 1) ^ s0)] & 0xFFFF0000u);
        float xl10 = __uint_as_float(X[m1 * 192 + (n ^ s1)] & 0xFFFF0000u);
        float xl11 = __uint_as_float(X[m1 * 192 + ((n + 1) ^ s1)] & 0xFFFF0000u);
        float y00 = d[nt][mt][0] + fmaf(xl00, w3d0, bias0);
        float y01 = d[nt][mt][1] + fmaf(xl01, w3d1, bias1);
        float y10 = d[nt][mt][2] + fmaf(xl10, w3d0, bias0);
        float y11 = d[nt][mt][3] + fmaf(xl11, w3d1, bias1);
        ldsum -= 0.5f * (y00 * y00 + y01 * y01 + y10 * y10 + y11 * y11);
        ob[n * 64 + m0]       = y00;
        ob[(n + 1) * 64 + m0] = y01;
        ob[n * 64 + m1]       = y10;
        ob[(n + 1) * 64 + m1] = y11;
      }
    }
  }

  // ---- per-sample log_pdf reduction ----
#pragma unroll
  for (int off = 16; off > 0; off >>= 1) ldsum += __shfl_down_sync(FULLMASK, ldsum, off);
  if (lane == 0) red[wid] = ldsum;
  __syncthreads();
  if (tid == 0) {
    float t = 0.f;
#pragma unroll
    for (int i = 0; i < 8; i++) t += red[i];
    out[NPIX + b] = t - 0.5f * 1.8378770664093453f * 12288.0f + g_convld;
  }
}

// ============================================================================
extern "C" void kernel_launch(void* const* d_in, const int* in_sizes, int n_in,
                              void* d_out, int out_size) {
  // map inputs by element count (all sizes distinct) — robust to ordering
  const float *x = 0, *k1 = 0, *b1 = 0, *k2 = 0, *b2 = 0, *k3 = 0, *b3 = 0;
  for (int i = 0; i < n_in; i++) {
    const float* p = (const float*)d_in[i];
    switch (in_sizes[i]) {
      case 512 * 12288:   x  = p; break;
      case 12 * 12 * 9:   k1 = p; break;
      case 12:            b1 = p; break;
      case 48 * 48 * 9:   k2 = p; break;
      case 48:            b2 = p; break;
      case 192 * 192 * 9: k3 = p; break;
      case 192:           b3 = p; break;
    }
  }
  float* out = (float*)d_out;

  const int SMEM_BYTES = 2 * 12288 * 4;   // 98304
  cudaFuncSetAttribute(k_main, cudaFuncAttributeMaxDynamicSharedMemorySize, SMEM_BYTES);

  k_pack<<<(9 * 8 * 12 * 3 * 32 + 255) / 256, 256>>>(k3);   // also zeroes g_convld
  k_logdet<<<160, 256>>>(k1, k2, k3);
  k_main<<<512, 256, SMEM_BYTES>>>(x, k1, b1, k2, b2, b3, out);
}